// round 15
// baseline (speedup 1.0000x reference)
#include <cuda_runtime.h>
#include <cuda_bf16.h>
#include <cstdint>

// Problem constants (fixed by the dataset)
#define NN 50000
#define EE 800000
#define F 128
#define CC 4

#define WROW 72
#define WSZ (128 * WROW)

// ---------------- device scratch (no allocation allowed) ----------------
__device__ __align__(128) int   g_cnt[NN];
__device__ __align__(128) int   g_fill[NN];
__device__ __align__(128) int   g_ptr[NN + 1];
__device__ __align__(128) int   g_idx[EE];
__device__ __align__(128) int   g_partial[NN];
__device__ __align__(128) int   g_bsum[256];
__device__ __align__(128) float g_invd[NN];
__device__ __align__(128) float g_y[(size_t)NN * F];
__device__ __align__(128) float g_r[(size_t)NN * F];
__device__ __align__(128) float g_z[(size_t)NN * CC];
__device__ __align__(128) float g_r2[(size_t)NN * CC];
// packed bf16 weights, n-major padded-permuted: word (kk,n) at [n*WROW + kkpos(kk)].
// 4 matrices: Wl0, Wr0, Wl1, Wr1; hi and lo split terms.
__device__ __align__(128) uint32_t g_wp_hi[4 * WSZ];
__device__ __align__(128) uint32_t g_wp_lo[4 * WSZ];
// pre-split A (hi/lo) in the same permuted row layout
__device__ __align__(128) uint32_t g_ahi[(size_t)NN * WROW];
__device__ __align__(128) uint32_t g_alo[(size_t)NN * WROW];

__device__ __forceinline__ int kkpos(int w) {
    return ((w >> 3) << 3) | ((w & 3) << 1) | ((w >> 2) & 1);
}

__device__ __forceinline__ uint32_t pack_bf2(float a, float b) {
    __nv_bfloat16 ha = __float2bfloat16(a);
    __nv_bfloat16 hb = __float2bfloat16(b);
    return (uint32_t)__bfloat16_as_ushort(ha) | ((uint32_t)__bfloat16_as_ushort(hb) << 16);
}

// ---------------- CSR build ----------------
__global__ void k_init(int n) {
    int i = blockIdx.x * blockDim.x + threadIdx.x;
    if (i < n) { g_cnt[i] = 0; g_fill[i] = 0; }
}

__global__ void k_hist(const int* __restrict__ dst, int e) {
    int i = blockIdx.x * blockDim.x + threadIdx.x;
    if (i < e) atomicAdd(&g_cnt[dst[i]], 1);
}

#define SCAN_B 512
__global__ void k_scan1(int n) {
    __shared__ int s[SCAN_B];
    int i = blockIdx.x * SCAN_B + threadIdx.x;
    int v = (i < n) ? g_cnt[i] : 0;
    s[threadIdx.x] = v;
    __syncthreads();
    #pragma unroll
    for (int off = 1; off < SCAN_B; off <<= 1) {
        int t = (threadIdx.x >= off) ? s[threadIdx.x - off] : 0;
        __syncthreads();
        s[threadIdx.x] += t;
        __syncthreads();
    }
    if (i < n) g_partial[i] = s[threadIdx.x];
    if (threadIdx.x == SCAN_B - 1) g_bsum[blockIdx.x] = s[threadIdx.x];
}

__global__ void k_scan2(int nb) {
    __shared__ int s[256];
    int v = (threadIdx.x < nb) ? g_bsum[threadIdx.x] : 0;
    s[threadIdx.x] = v;
    __syncthreads();
    #pragma unroll
    for (int off = 1; off < 256; off <<= 1) {
        int t = (threadIdx.x >= off) ? s[threadIdx.x - off] : 0;
        __syncthreads();
        s[threadIdx.x] += t;
        __syncthreads();
    }
    if (threadIdx.x < nb) g_bsum[threadIdx.x] = s[threadIdx.x] - v;  // exclusive
}

__global__ void k_scan3(int n) {
    int i = blockIdx.x * SCAN_B + threadIdx.x;
    if (i < n) {
        int inc = g_partial[i] + g_bsum[blockIdx.x];
        g_ptr[i + 1] = inc;
        int c = g_cnt[i];
        g_invd[i] = (c > 0) ? (1.0f / (float)c) : 0.0f;
        if (i == 0) g_ptr[0] = 0;
    }
}

__global__ void k_fill(const int* __restrict__ src, const int* __restrict__ dst, int e) {
    int i = blockIdx.x * blockDim.x + threadIdx.x;
    if (i < e) {
        int d = dst[i];
        int p = g_ptr[d] + atomicAdd(&g_fill[d], 1);
        g_idx[p] = src[i];
    }
}

// ---------------- weight prep: 4 matrices in one launch ----------------
__global__ void k_prepW4(const float* __restrict__ W0, const float* __restrict__ W1,
                         const float* __restrict__ W2, const float* __restrict__ W3) {
    int i = blockIdx.x * blockDim.x + threadIdx.x;  // 0..8191
    if (i >= 64 * F) return;
    int m = blockIdx.y;
    const float* W = (m == 0) ? W0 : (m == 1) ? W1 : (m == 2) ? W2 : W3;
    int kk = i >> 7, n = i & 127;
    float w0 = W[(2 * kk) * F + n];
    float w1 = W[(2 * kk + 1) * F + n];
    __nv_bfloat16 h0 = __float2bfloat16(w0), h1 = __float2bfloat16(w1);
    float r0 = w0 - __bfloat162float(h0);
    float r1 = w1 - __bfloat162float(h1);
    int pos = m * WSZ + n * WROW + kkpos(kk);
    g_wp_hi[pos] = (uint32_t)__bfloat16_as_ushort(h0) | ((uint32_t)__bfloat16_as_ushort(h1) << 16);
    g_wp_lo[pos] = pack_bf2(r0, r1);
}

// ---------------- A prep: fp32 [M,128] -> packed bf16 hi/lo, permuted rows -------
__global__ void k_prepA(const float* __restrict__ A, int M) {
    int i = blockIdx.x * blockDim.x + threadIdx.x;
    if (i >= M * 32) return;
    int row = i >> 5;
    int c4 = (i & 31) * 4;
    float4 v = *(const float4*)(A + (size_t)row * F + c4);
    float hx = __bfloat162float(__float2bfloat16(v.x));
    float hy = __bfloat162float(__float2bfloat16(v.y));
    float hz = __bfloat162float(__float2bfloat16(v.z));
    float hw = __bfloat162float(__float2bfloat16(v.w));
    int w0 = (i & 31) * 2;
    size_t p0 = (size_t)row * WROW + kkpos(w0);
    size_t p1 = (size_t)row * WROW + kkpos(w0 + 1);
    g_ahi[p0] = pack_bf2(v.x, v.y);
    g_ahi[p1] = pack_bf2(v.z, v.w);
    g_alo[p0] = pack_bf2(v.x - hx, v.y - hy);
    g_alo[p1] = pack_bf2(v.z - hz, v.w - hw);
}

// ---------------- mma.sync bf16 GEMM (3-term split): Y = A @ W -------------------
// Block: 64 rows x 64 cols, 256 threads (8 warps: 2 m-groups x 4 n-groups of 16).
// grid.y in 0..3: wsel = y>>1 (Wl/Wr), half = y&1 (n-half of the 128 output cols).
// Smem 73.7KB -> 3 CTAs/SM.  Mainloop register double-buffered (prefetch ks+1).
#define SM_AHI 0
#define SM_ALO 18432
#define SM_BHI 36864
#define SM_BLO 55296
#define SM_GEMM_TOTAL 73728

__device__ __forceinline__ void mma_bf16(float* c, const uint32_t* a, const uint32_t* b) {
    asm volatile(
        "mma.sync.aligned.m16n8k16.row.col.f32.bf16.bf16.f32 "
        "{%0,%1,%2,%3}, {%4,%5,%6,%7}, {%8,%9}, {%0,%1,%2,%3};"
        : "+f"(c[0]), "+f"(c[1]), "+f"(c[2]), "+f"(c[3])
        : "r"(a[0]), "r"(a[1]), "r"(a[2]), "r"(a[3]), "r"(b[0]), "r"(b[1]));
}

__global__ __launch_bounds__(256, 3)
void k_mma64(const uint32_t* __restrict__ whi, const uint32_t* __restrict__ wlo,
             float* __restrict__ Yl, float* __restrict__ Yr, int M) {
    extern __shared__ char smem[];
    const int tid = threadIdx.x;
    const int wid = tid >> 5;
    const int lane = tid & 31;
    const int rowBase = blockIdx.x * 64;
    const int wsel = blockIdx.y >> 1;
    const int half = blockIdx.y & 1;

    const uint32_t* Bhi = whi + wsel * WSZ + half * 64 * WROW;
    const uint32_t* Blo = wlo + wsel * WSZ + half * 64 * WROW;
    float* Y = wsel ? Yr : Yl;
    const int colBase = half * 64;

    // ---- stage A (pre-split, guarded) and B (unguarded) via uint4 copies ----
    const uint32_t* Ahi = g_ahi + (size_t)rowBase * WROW;
    const uint32_t* Alo = g_alo + (size_t)rowBase * WROW;
    const int rowsValid = M - rowBase;   // >= 1
    for (int idx = tid; idx < 64 * (WROW / 4); idx += 256) {
        int row = idx / (WROW / 4);
        int q = idx % (WROW / 4);
        uint4 vh = make_uint4(0, 0, 0, 0), vl = make_uint4(0, 0, 0, 0);
        if (row < rowsValid) {
            vh = *(const uint4*)(Ahi + (size_t)row * WROW + q * 4);
            vl = *(const uint4*)(Alo + (size_t)row * WROW + q * 4);
        }
        *(uint4*)(smem + SM_AHI + idx * 16) = vh;
        *(uint4*)(smem + SM_ALO + idx * 16) = vl;
        *(uint4*)(smem + SM_BHI + idx * 16) = *(const uint4*)(Bhi + idx * 4);
        *(uint4*)(smem + SM_BLO + idx * 16) = *(const uint4*)(Blo + idx * 4);
    }
    __syncthreads();

    const int m0 = (wid & 1) * 32;
    const int n0 = (wid >> 1) * 16;

    float acc[2][2][4];
    #pragma unroll
    for (int t = 0; t < 2; t++)
        #pragma unroll
        for (int j = 0; j < 2; j++)
            #pragma unroll
            for (int q = 0; q < 4; q++) acc[t][j][q] = 0.0f;

    const int r_lo = lane >> 2;
    const int kc = lane & 3;

    // per-iteration fragment loader
    uint32_t ah[2][2][4], al[2][2][4], bh[2][2][2], bl[2][2][2];
    #define LOAD_FRAG(buf, ks) do {                                                        \
        _Pragma("unroll")                                                                   \
        for (int t = 0; t < 2; t++) {                                                       \
            uint32_t w0 = (uint32_t)((m0 + t * 16 + r_lo) * WROW + (ks) * 8 + 2 * kc) * 4;  \
            uint2 p = *(const uint2*)(smem + SM_AHI + w0);                                  \
            uint2 q = *(const uint2*)(smem + SM_AHI + w0 + 8 * WROW * 4);                   \
            ah[buf][t][0] = p.x; ah[buf][t][1] = q.x; ah[buf][t][2] = p.y; ah[buf][t][3] = q.y; \
            p = *(const uint2*)(smem + SM_ALO + w0);                                        \
            q = *(const uint2*)(smem + SM_ALO + w0 + 8 * WROW * 4);                         \
            al[buf][t][0] = p.x; al[buf][t][1] = q.x; al[buf][t][2] = p.y; al[buf][t][3] = q.y; \
        }                                                                                   \
        _Pragma("unroll")                                                                   \
        for (int j = 0; j < 2; j++) {                                                       \
            uint32_t wo = (uint32_t)((n0 + j * 8 + r_lo) * WROW + (ks) * 8 + 2 * kc) * 4;   \
            uint2 b = *(const uint2*)(smem + SM_BHI + wo);                                  \
            bh[buf][j][0] = b.x; bh[buf][j][1] = b.y;                                       \
            b = *(const uint2*)(smem + SM_BLO + wo);                                        \
            bl[buf][j][0] = b.x; bl[buf][j][1] = b.y;                                       \
        }                                                                                   \
    } while (0)

    LOAD_FRAG(0, 0);
    #pragma unroll
    for (int ks = 0; ks < 8; ks++) {
        const int cur = ks & 1;
        if (ks < 7) LOAD_FRAG(1 - cur, ks + 1);
        #pragma unroll
        for (int t = 0; t < 2; t++)
            #pragma unroll
            for (int j = 0; j < 2; j++) mma_bf16(acc[t][j], ah[cur][t], bh[cur][j]);
        #pragma unroll
        for (int t = 0; t < 2; t++)
            #pragma unroll
            for (int j = 0; j < 2; j++) mma_bf16(acc[t][j], al[cur][t], bh[cur][j]);
        #pragma unroll
        for (int t = 0; t < 2; t++)
            #pragma unroll
            for (int j = 0; j < 2; j++) mma_bf16(acc[t][j], ah[cur][t], bl[cur][j]);
    }
    #undef LOAD_FRAG

    // ---- epilogue ----
    #pragma unroll
    for (int t = 0; t < 2; t++) {
        int row0 = rowBase + m0 + t * 16 + r_lo;
        #pragma unroll
        for (int j = 0; j < 2; j++) {
            int col = colBase + n0 + j * 8 + 2 * kc;
            if (row0 < M)
                *(float2*)(Y + (size_t)row0 * F + col) = make_float2(acc[t][j][0], acc[t][j][1]);
            if (row0 + 8 < M)
                *(float2*)(Y + (size_t)(row0 + 8) * F + col) = make_float2(acc[t][j][2], acc[t][j][3]);
        }
    }
}

// ---------------- 128-wide aggregation, fused epilogues -------------------------
// row = agg(Y)[n]*invd + bias + R[n]  (+relu)
// writePacked: emit bf16 hi/lo permuted row into g_ahi/g_alo (next layer's A); no fp32 out.
// else: write fp32 O; if Wl2 != null, also fused tiny GEMM -> g_z, g_r2.
__global__ void k_agg128(const float* __restrict__ Y, const float* __restrict__ R,
                         const float* __restrict__ bias, float* __restrict__ O,
                         int n, int doRelu, int writePacked,
                         const float* __restrict__ Wl2, const float* __restrict__ Wr2) {
    __shared__ float sWl[F * CC];
    __shared__ float sWr[F * CC];
    int tid = threadIdx.x;
    if (Wl2) {
        for (int i = tid; i < F * CC; i += blockDim.x) { sWl[i] = Wl2[i]; sWr[i] = Wr2[i]; }
        __syncthreads();
    }
    int gwarp = (blockIdx.x * blockDim.x + tid) >> 5;
    int lane = tid & 31;
    if (gwarp >= n) return;
    int s = g_ptr[gwarp], e = g_ptr[gwarp + 1];
    float4 a0 = make_float4(0.f, 0.f, 0.f, 0.f);
    float4 a1 = make_float4(0.f, 0.f, 0.f, 0.f);
    int i = s;
    for (; i + 1 < e; i += 2) {
        int n0 = g_idx[i], n1 = g_idx[i + 1];
        float4 v0 = *(const float4*)(Y + (size_t)n0 * F + lane * 4);
        float4 v1 = *(const float4*)(Y + (size_t)n1 * F + lane * 4);
        a0.x += v0.x; a0.y += v0.y; a0.z += v0.z; a0.w += v0.w;
        a1.x += v1.x; a1.y += v1.y; a1.z += v1.z; a1.w += v1.w;
    }
    if (i < e) {
        int n0 = g_idx[i];
        float4 v0 = *(const float4*)(Y + (size_t)n0 * F + lane * 4);
        a0.x += v0.x; a0.y += v0.y; a0.z += v0.z; a0.w += v0.w;
    }
    a0.x += a1.x; a0.y += a1.y; a0.z += a1.z; a0.w += a1.w;
    float id = g_invd[gwarp];
    float4 rv = *(const float4*)(R + (size_t)gwarp * F + lane * 4);
    float4 bv = *(const float4*)(bias + lane * 4);
    float4 o;
    o.x = a0.x * id + bv.x + rv.x;
    o.y = a0.y * id + bv.y + rv.y;
    o.z = a0.z * id + bv.z + rv.z;
    o.w = a0.w * id + bv.w + rv.w;
    if (doRelu) {
        o.x = fmaxf(o.x, 0.f); o.y = fmaxf(o.y, 0.f);
        o.z = fmaxf(o.z, 0.f); o.w = fmaxf(o.w, 0.f);
    }

    if (writePacked) {
        // split to bf16 hi/lo and store in the permuted packed-A layout
        float hx = __bfloat162float(__float2bfloat16(o.x));
        float hy = __bfloat162float(__float2bfloat16(o.y));
        float hz = __bfloat162float(__float2bfloat16(o.z));
        float hw = __bfloat162float(__float2bfloat16(o.w));
        size_t p0 = (size_t)gwarp * WROW + kkpos(2 * lane);
        size_t p1 = (size_t)gwarp * WROW + kkpos(2 * lane + 1);
        g_ahi[p0] = pack_bf2(o.x, o.y);
        g_ahi[p1] = pack_bf2(o.z, o.w);
        g_alo[p0] = pack_bf2(o.x - hx, o.y - hy);
        g_alo[p1] = pack_bf2(o.z - hz, o.w - hw);
        return;
    }

    *(float4*)(O + (size_t)gwarp * F + lane * 4) = o;

    if (Wl2) {
        // fused tiny GEMM: z = o @ Wl2, r2 = o @ Wr2  (full row is in this warp)
        float ov[4] = { o.x, o.y, o.z, o.w };
        float zl[4] = { 0.f, 0.f, 0.f, 0.f };
        float zr[4] = { 0.f, 0.f, 0.f, 0.f };
        #pragma unroll
        for (int c = 0; c < 4; c++) {
            int k = lane * 4 + c;
            #pragma unroll
            for (int j = 0; j < 4; j++) {
                zl[j] += ov[c] * sWl[k * CC + j];
                zr[j] += ov[c] * sWr[k * CC + j];
            }
        }
        #pragma unroll
        for (int off = 16; off > 0; off >>= 1) {
            #pragma unroll
            for (int j = 0; j < 4; j++) {
                zl[j] += __shfl_down_sync(0xFFFFFFFFu, zl[j], off);
                zr[j] += __shfl_down_sync(0xFFFFFFFFu, zr[j], off);
            }
        }
        if (lane == 0) {
            *(float4*)(g_z  + (size_t)gwarp * CC) = make_float4(zl[0], zl[1], zl[2], zl[3]);
            *(float4*)(g_r2 + (size_t)gwarp * CC) = make_float4(zr[0], zr[1], zr[2], zr[3]);
        }
    }
}

// ---------------- 4-wide aggregation + final epilogue; writes out twice ----------------
__global__ void k_agg4(const float* __restrict__ b2, float* __restrict__ out, int n) {
    int gwarp = (blockIdx.x * blockDim.x + threadIdx.x) >> 5;
    int lane = threadIdx.x & 31;
    if (gwarp >= n) return;
    int s = g_ptr[gwarp], e = g_ptr[gwarp + 1];
    float4 acc = make_float4(0.f, 0.f, 0.f, 0.f);
    for (int i = s + lane; i < e; i += 32) {
        int nb = g_idx[i];
        float4 z = *(const float4*)(g_z + (size_t)nb * CC);
        acc.x += z.x; acc.y += z.y; acc.z += z.z; acc.w += z.w;
    }
    #pragma unroll
    for (int off = 16; off > 0; off >>= 1) {
        acc.x += __shfl_xor_sync(0xFFFFFFFFu, acc.x, off);
        acc.y += __shfl_xor_sync(0xFFFFFFFFu, acc.y, off);
        acc.z += __shfl_xor_sync(0xFFFFFFFFu, acc.z, off);
        acc.w += __shfl_xor_sync(0xFFFFFFFFu, acc.w, off);
    }
    if (lane == 0) {
        float id = g_invd[gwarp];
        float4 r = *(const float4*)(g_r2 + (size_t)gwarp * CC);
        float4 b = *(const float4*)(b2);
        float4 o;
        o.x = acc.x * id + b.x + r.x;
        o.y = acc.y * id + b.y + r.y;
        o.z = acc.z * id + b.z + r.z;
        o.w = acc.w * id + b.w + r.w;
        *(float4*)(out + (size_t)gwarp * CC) = o;
        *(float4*)(out + (size_t)n * CC + (size_t)gwarp * CC) = o;
    }
}

// ---------------- launch ----------------
static cudaStream_t g_s2 = nullptr;
static cudaEvent_t g_eFork = nullptr;
static cudaEvent_t g_eW = nullptr;
static cudaEvent_t g_eJoin = nullptr;

extern "C" void kernel_launch(void* const* d_in, const int* in_sizes, int n_in,
                              void* d_out, int out_size) {
    const float* x   = (const float*)d_in[0];
    const int*   ei  = (const int*)d_in[1];
    const float* Wl0 = (const float*)d_in[2];
    const float* bl0 = (const float*)d_in[3];
    const float* Wr0 = (const float*)d_in[4];
    const float* Wl1 = (const float*)d_in[5];
    const float* bl1 = (const float*)d_in[6];
    const float* Wr1 = (const float*)d_in[7];
    const float* Wl2 = (const float*)d_in[8];
    const float* bl2 = (const float*)d_in[9];
    const float* Wr2 = (const float*)d_in[10];

    int N = in_sizes[0] / F;
    int E = in_sizes[1] / 2;
    const int* src = ei;
    const int* dst = ei + E;

    float* out = (float*)d_out;
    float* h2  = out + (size_t)2 * N * CC;   // layout: out | out | h2

    void* p;
    cudaGetSymbolAddress(&p, g_y);  float* yb = (float*)p;
    cudaGetSymbolAddress(&p, g_r);  float* rb = (float*)p;
    cudaGetSymbolAddress(&p, g_wp_hi); uint32_t* whi = (uint32_t*)p;
    cudaGetSymbolAddress(&p, g_wp_lo); uint32_t* wlo = (uint32_t*)p;

    if (!g_s2) {
        cudaStreamCreateWithFlags(&g_s2, cudaStreamNonBlocking);
        cudaEventCreateWithFlags(&g_eFork, cudaEventDisableTiming);
        cudaEventCreateWithFlags(&g_eW, cudaEventDisableTiming);
        cudaEventCreateWithFlags(&g_eJoin, cudaEventDisableTiming);
    }

    cudaFuncSetAttribute(k_mma64, cudaFuncAttributeMaxDynamicSharedMemorySize, SM_GEMM_TOTAL);

    int gemmBlocks = (N + 63) / 64;
    int warpBlocks = (N * 32 + 255) / 256;
    int nScanBlocks = (N + SCAN_B - 1) / SCAN_B;

    // ---- fork: weight prep + CSR build on g_s2, A prep + GEMM on main stream ----
    cudaEventRecord(g_eFork, 0);
    cudaStreamWaitEvent(g_s2, g_eFork, 0);

    // branch B (g_s2): weight prep first (needed by GEMM), then CSR chain
    k_prepW4<<<dim3(32, 4), 256, 0, g_s2>>>(Wl0, Wr0, Wl1, Wr1);
    cudaEventRecord(g_eW, g_s2);
    k_init<<<(N + 255) / 256, 256, 0, g_s2>>>(N);
    k_hist<<<(E + 255) / 256, 256, 0, g_s2>>>(dst, E);
    k_scan1<<<nScanBlocks, SCAN_B, 0, g_s2>>>(N);
    k_scan2<<<1, 256, 0, g_s2>>>(nScanBlocks);
    k_scan3<<<nScanBlocks, SCAN_B, 0, g_s2>>>(N);
    k_fill<<<(E + 255) / 256, 256, 0, g_s2>>>(src, dst, E);
    cudaEventRecord(g_eJoin, g_s2);

    // branch A (main stream): A prep, then layer-0 GEMM (waits for weights)
    k_prepA<<<(N * 32 + 255) / 256, 256>>>(x, N);
    cudaStreamWaitEvent(0, g_eW, 0);
    k_mma64<<<dim3(gemmBlocks, 4), 256, SM_GEMM_TOTAL>>>(whi, wlo, yb, rb, N);

    // ---- join: aggregation needs both CSR (g_ptr/invd/idx) and y/r ----
    cudaStreamWaitEvent(0, g_eJoin, 0);

    // layer 0 aggregation -> packed bf16 A for layer 1 (h never materialized fp32)
    k_agg128<<<warpBlocks, 256>>>(yb, rb, bl0, nullptr, N, 1, 1, nullptr, nullptr);

    // layer 1: GEMM directly from packed A, then aggregation with fused layer-2 tiny GEMM
    k_mma64<<<dim3(gemmBlocks, 4), 256, SM_GEMM_TOTAL>>>(whi + 2 * WSZ, wlo + 2 * WSZ, yb, rb, N);
    k_agg128<<<warpBlocks, 256>>>(yb, rb, bl1, h2, N, 0, 0, Wl2, Wr2);

    // layer 2 aggregation: out = agg(z)*invd + bl2 + r2 (written twice)
    k_agg4<<<warpBlocks, 256>>>(bl2, out, N);
}

// round 17
// speedup vs baseline: 1.0389x; 1.0389x over previous
#include <cuda_runtime.h>
#include <cuda_bf16.h>
#include <cuda_fp16.h>
#include <cstdint>

// Problem constants (fixed by the dataset)
#define NN 50000
#define EE 800000
#define F 128
#define CC 4

#define WROW 72
#define WSZ (128 * WROW)

// ---------------- device scratch (no allocation allowed) ----------------
__device__ __align__(128) int   g_cnt[NN];
__device__ __align__(128) int   g_fill[NN];
__device__ __align__(128) int   g_ptr[NN + 1];
__device__ __align__(128) int   g_idx[EE];
__device__ __align__(128) int   g_partial[NN];
__device__ __align__(128) int   g_bsum[256];
__device__ __align__(128) float g_invd[NN];
__device__ __align__(128) uint32_t g_y16[(size_t)NN * (F / 2)];   // Yl as half2 words
__device__ __align__(128) float g_r[(size_t)NN * F];              // Yr residual, fp32
__device__ __align__(128) float g_z[(size_t)NN * CC];
__device__ __align__(128) float g_r2[(size_t)NN * CC];
// packed bf16 weights, n-major padded-permuted: word (kk,n) at [n*WROW + kkpos(kk)].
// 4 matrices: Wl0, Wr0, Wl1, Wr1; hi and lo split terms.
__device__ __align__(128) uint32_t g_wp_hi[4 * WSZ];
__device__ __align__(128) uint32_t g_wp_lo[4 * WSZ];
// pre-split A (hi/lo) in the same permuted row layout
__device__ __align__(128) uint32_t g_ahi[(size_t)NN * WROW];
__device__ __align__(128) uint32_t g_alo[(size_t)NN * WROW];

__device__ __forceinline__ int kkpos(int w) {
    return ((w >> 3) << 3) | ((w & 3) << 1) | ((w >> 2) & 1);
}

__device__ __forceinline__ uint32_t pack_bf2(float a, float b) {
    __nv_bfloat16 ha = __float2bfloat16(a);
    __nv_bfloat16 hb = __float2bfloat16(b);
    return (uint32_t)__bfloat16_as_ushort(ha) | ((uint32_t)__bfloat16_as_ushort(hb) << 16);
}

// ---------------- CSR build ----------------
__global__ void k_init(int n) {
    int i = blockIdx.x * blockDim.x + threadIdx.x;
    if (i < n) { g_cnt[i] = 0; g_fill[i] = 0; }
}

__global__ void k_hist(const int* __restrict__ dst, int e) {
    int i = blockIdx.x * blockDim.x + threadIdx.x;
    if (i < e) atomicAdd(&g_cnt[dst[i]], 1);
}

#define SCAN_B 512
__global__ void k_scan1(int n) {
    __shared__ int s[SCAN_B];
    int i = blockIdx.x * SCAN_B + threadIdx.x;
    int v = (i < n) ? g_cnt[i] : 0;
    s[threadIdx.x] = v;
    __syncthreads();
    #pragma unroll
    for (int off = 1; off < SCAN_B; off <<= 1) {
        int t = (threadIdx.x >= off) ? s[threadIdx.x - off] : 0;
        __syncthreads();
        s[threadIdx.x] += t;
        __syncthreads();
    }
    if (i < n) g_partial[i] = s[threadIdx.x];
    if (threadIdx.x == SCAN_B - 1) g_bsum[blockIdx.x] = s[threadIdx.x];
}

__global__ void k_scan2(int nb) {
    __shared__ int s[256];
    int v = (threadIdx.x < nb) ? g_bsum[threadIdx.x] : 0;
    s[threadIdx.x] = v;
    __syncthreads();
    #pragma unroll
    for (int off = 1; off < 256; off <<= 1) {
        int t = (threadIdx.x >= off) ? s[threadIdx.x - off] : 0;
        __syncthreads();
        s[threadIdx.x] += t;
        __syncthreads();
    }
    if (threadIdx.x < nb) g_bsum[threadIdx.x] = s[threadIdx.x] - v;  // exclusive
}

__global__ void k_scan3(int n) {
    int i = blockIdx.x * SCAN_B + threadIdx.x;
    if (i < n) {
        int inc = g_partial[i] + g_bsum[blockIdx.x];
        g_ptr[i + 1] = inc;
        int c = g_cnt[i];
        g_invd[i] = (c > 0) ? (1.0f / (float)c) : 0.0f;
        if (i == 0) g_ptr[0] = 0;
    }
}

__global__ void k_fill(const int* __restrict__ src, const int* __restrict__ dst, int e) {
    int i = blockIdx.x * blockDim.x + threadIdx.x;
    if (i < e) {
        int d = dst[i];
        int p = g_ptr[d] + atomicAdd(&g_fill[d], 1);
        g_idx[p] = src[i];
    }
}

// ---------------- weight prep: 4 matrices in one launch ----------------
__global__ void k_prepW4(const float* __restrict__ W0, const float* __restrict__ W1,
                         const float* __restrict__ W2, const float* __restrict__ W3) {
    int i = blockIdx.x * blockDim.x + threadIdx.x;  // 0..8191
    if (i >= 64 * F) return;
    int m = blockIdx.y;
    const float* W = (m == 0) ? W0 : (m == 1) ? W1 : (m == 2) ? W2 : W3;
    int kk = i >> 7, n = i & 127;
    float w0 = W[(2 * kk) * F + n];
    float w1 = W[(2 * kk + 1) * F + n];
    __nv_bfloat16 h0 = __float2bfloat16(w0), h1 = __float2bfloat16(w1);
    float r0 = w0 - __bfloat162float(h0);
    float r1 = w1 - __bfloat162float(h1);
    int pos = m * WSZ + n * WROW + kkpos(kk);
    g_wp_hi[pos] = (uint32_t)__bfloat16_as_ushort(h0) | ((uint32_t)__bfloat16_as_ushort(h1) << 16);
    g_wp_lo[pos] = pack_bf2(r0, r1);
}

// ---------------- A prep: fp32 [M,128] -> packed bf16 hi/lo, permuted rows -------
__global__ void k_prepA(const float* __restrict__ A, int M) {
    int i = blockIdx.x * blockDim.x + threadIdx.x;
    if (i >= M * 32) return;
    int row = i >> 5;
    int c4 = (i & 31) * 4;
    float4 v = *(const float4*)(A + (size_t)row * F + c4);
    float hx = __bfloat162float(__float2bfloat16(v.x));
    float hy = __bfloat162float(__float2bfloat16(v.y));
    float hz = __bfloat162float(__float2bfloat16(v.z));
    float hw = __bfloat162float(__float2bfloat16(v.w));
    int w0 = (i & 31) * 2;
    size_t p0 = (size_t)row * WROW + kkpos(w0);
    size_t p1 = (size_t)row * WROW + kkpos(w0 + 1);
    g_ahi[p0] = pack_bf2(v.x, v.y);
    g_ahi[p1] = pack_bf2(v.z, v.w);
    g_alo[p0] = pack_bf2(v.x - hx, v.y - hy);
    g_alo[p1] = pack_bf2(v.z - hz, v.w - hw);
}

// ---------------- mma.sync bf16 GEMM (3-term split): Y = A @ W -------------------
// Block: 64 rows x 64 cols, 256 threads (8 warps: 2 m-groups x 4 n-groups of 16).
// grid.y in 0..3: wsel = y>>1 (Wl -> Yl fp16 / Wr -> Yr fp32), half = y&1.
// Smem 73.7KB -> 3 CTAs/SM.  (R14 mainloop — accepted as final.)
#define SM_AHI 0
#define SM_ALO 18432
#define SM_BHI 36864
#define SM_BLO 55296
#define SM_GEMM_TOTAL 73728

__device__ __forceinline__ void mma_bf16(float* c, const uint32_t* a, const uint32_t* b) {
    asm volatile(
        "mma.sync.aligned.m16n8k16.row.col.f32.bf16.bf16.f32 "
        "{%0,%1,%2,%3}, {%4,%5,%6,%7}, {%8,%9}, {%0,%1,%2,%3};"
        : "+f"(c[0]), "+f"(c[1]), "+f"(c[2]), "+f"(c[3])
        : "r"(a[0]), "r"(a[1]), "r"(a[2]), "r"(a[3]), "r"(b[0]), "r"(b[1]));
}

__global__ __launch_bounds__(256, 3)
void k_mma64(const uint32_t* __restrict__ whi, const uint32_t* __restrict__ wlo,
             uint32_t* __restrict__ Yl16, float* __restrict__ Yr, int M) {
    extern __shared__ char smem[];
    const int tid = threadIdx.x;
    const int wid = tid >> 5;
    const int lane = tid & 31;
    const int rowBase = blockIdx.x * 64;
    const int wsel = blockIdx.y >> 1;
    const int half = blockIdx.y & 1;

    const uint32_t* Bhi = whi + wsel * WSZ + half * 64 * WROW;
    const uint32_t* Blo = wlo + wsel * WSZ + half * 64 * WROW;
    const int colBase = half * 64;

    // ---- stage A (pre-split, guarded) and B (unguarded) via uint4 copies ----
    const uint32_t* Ahi = g_ahi + (size_t)rowBase * WROW;
    const uint32_t* Alo = g_alo + (size_t)rowBase * WROW;
    const int rowsValid = M - rowBase;   // >= 1
    for (int idx = tid; idx < 64 * (WROW / 4); idx += 256) {
        int row = idx / (WROW / 4);
        int q = idx % (WROW / 4);
        uint4 vh = make_uint4(0, 0, 0, 0), vl = make_uint4(0, 0, 0, 0);
        if (row < rowsValid) {
            vh = *(const uint4*)(Ahi + (size_t)row * WROW + q * 4);
            vl = *(const uint4*)(Alo + (size_t)row * WROW + q * 4);
        }
        *(uint4*)(smem + SM_AHI + idx * 16) = vh;
        *(uint4*)(smem + SM_ALO + idx * 16) = vl;
        *(uint4*)(smem + SM_BHI + idx * 16) = *(const uint4*)(Bhi + idx * 4);
        *(uint4*)(smem + SM_BLO + idx * 16) = *(const uint4*)(Blo + idx * 4);
    }
    __syncthreads();

    const int m0 = (wid & 1) * 32;
    const int n0 = (wid >> 1) * 16;

    float acc[2][2][4];
    #pragma unroll
    for (int t = 0; t < 2; t++)
        #pragma unroll
        for (int j = 0; j < 2; j++)
            #pragma unroll
            for (int q = 0; q < 4; q++) acc[t][j][q] = 0.0f;

    const int r_lo = lane >> 2;
    const int kc = lane & 3;

    #pragma unroll
    for (int ks = 0; ks < 8; ks++) {
        uint32_t ah[2][4], al[2][4];
        #pragma unroll
        for (int t = 0; t < 2; t++) {
            uint32_t w0 = (uint32_t)((m0 + t * 16 + r_lo) * WROW + ks * 8 + 2 * kc) * 4;
            uint2 p = *(const uint2*)(smem + SM_AHI + w0);
            uint2 q = *(const uint2*)(smem + SM_AHI + w0 + 8 * WROW * 4);
            ah[t][0] = p.x; ah[t][1] = q.x; ah[t][2] = p.y; ah[t][3] = q.y;
            p = *(const uint2*)(smem + SM_ALO + w0);
            q = *(const uint2*)(smem + SM_ALO + w0 + 8 * WROW * 4);
            al[t][0] = p.x; al[t][1] = q.x; al[t][2] = p.y; al[t][3] = q.y;
        }
        uint32_t bh[2][2], bl[2][2];
        #pragma unroll
        for (int j = 0; j < 2; j++) {
            uint32_t wo = (uint32_t)((n0 + j * 8 + r_lo) * WROW + ks * 8 + 2 * kc) * 4;
            uint2 b = *(const uint2*)(smem + SM_BHI + wo);
            bh[j][0] = b.x; bh[j][1] = b.y;
            b = *(const uint2*)(smem + SM_BLO + wo);
            bl[j][0] = b.x; bl[j][1] = b.y;
        }
        #pragma unroll
        for (int t = 0; t < 2; t++)
            #pragma unroll
            for (int j = 0; j < 2; j++) mma_bf16(acc[t][j], ah[t], bh[j]);
        #pragma unroll
        for (int t = 0; t < 2; t++)
            #pragma unroll
            for (int j = 0; j < 2; j++) mma_bf16(acc[t][j], al[t], bh[j]);
        #pragma unroll
        for (int t = 0; t < 2; t++)
            #pragma unroll
            for (int j = 0; j < 2; j++) mma_bf16(acc[t][j], ah[t], bl[j]);
    }

    // ---- epilogue: Yl -> fp16 half2 words, Yr -> fp32 ----
    if (wsel == 0) {
        #pragma unroll
        for (int t = 0; t < 2; t++) {
            int row0 = rowBase + m0 + t * 16 + r_lo;
            #pragma unroll
            for (int j = 0; j < 2; j++) {
                int colw = (colBase + n0 + j * 8 + 2 * kc) >> 1;
                __half2 h0 = __floats2half2_rn(acc[t][j][0], acc[t][j][1]);
                __half2 h1 = __floats2half2_rn(acc[t][j][2], acc[t][j][3]);
                if (row0 < M)     Yl16[(size_t)row0 * (F / 2) + colw] = *(uint32_t*)&h0;
                if (row0 + 8 < M) Yl16[(size_t)(row0 + 8) * (F / 2) + colw] = *(uint32_t*)&h1;
            }
        }
    } else {
        #pragma unroll
        for (int t = 0; t < 2; t++) {
            int row0 = rowBase + m0 + t * 16 + r_lo;
            #pragma unroll
            for (int j = 0; j < 2; j++) {
                int col = colBase + n0 + j * 8 + 2 * kc;
                if (row0 < M)
                    *(float2*)(Yr + (size_t)row0 * F + col) = make_float2(acc[t][j][0], acc[t][j][1]);
                if (row0 + 8 < M)
                    *(float2*)(Yr + (size_t)(row0 + 8) * F + col) = make_float2(acc[t][j][2], acc[t][j][3]);
            }
        }
    }
}

// ---------------- 128-wide aggregation (fp16 gather), fused epilogues -----------
// row = agg(Y16)[n]*invd + bias + R[n]  (+relu)
// writePacked: emit bf16 hi/lo permuted row into g_ahi/g_alo (next layer's A).
// else: write fp32 O; if Wl2 != null, also fused tiny GEMM -> g_z, g_r2.
__global__ void k_agg128(const uint32_t* __restrict__ Y16, const float* __restrict__ R,
                         const float* __restrict__ bias, float* __restrict__ O,
                         int n, int doRelu, int writePacked,
                         const float* __restrict__ Wl2, const float* __restrict__ Wr2) {
    __shared__ float sWl[F * CC];
    __shared__ float sWr[F * CC];
    int tid = threadIdx.x;
    if (Wl2) {
        for (int i = tid; i < F * CC; i += blockDim.x) { sWl[i] = Wl2[i]; sWr[i] = Wr2[i]; }
        __syncthreads();
    }
    int gwarp = (blockIdx.x * blockDim.x + tid) >> 5;
    int lane = tid & 31;
    if (gwarp >= n) return;
    int s = g_ptr[gwarp], e = g_ptr[gwarp + 1];
    float4 a0 = make_float4(0.f, 0.f, 0.f, 0.f);
    float4 a1 = make_float4(0.f, 0.f, 0.f, 0.f);
    int i = s;
    for (; i + 1 < e; i += 2) {
        int n0 = g_idx[i], n1 = g_idx[i + 1];
        uint2 v0 = *(const uint2*)(Y16 + (size_t)n0 * (F / 2) + lane * 2);
        uint2 v1 = *(const uint2*)(Y16 + (size_t)n1 * (F / 2) + lane * 2);
        float2 f;
        f = __half22float2(*(__half2*)&v0.x); a0.x += f.x; a0.y += f.y;
        f = __half22float2(*(__half2*)&v0.y); a0.z += f.x; a0.w += f.y;
        f = __half22float2(*(__half2*)&v1.x); a1.x += f.x; a1.y += f.y;
        f = __half22float2(*(__half2*)&v1.y); a1.z += f.x; a1.w += f.y;
    }
    if (i < e) {
        int n0 = g_idx[i];
        uint2 v0 = *(const uint2*)(Y16 + (size_t)n0 * (F / 2) + lane * 2);
        float2 f;
        f = __half22float2(*(__half2*)&v0.x); a0.x += f.x; a0.y += f.y;
        f = __half22float2(*(__half2*)&v0.y); a0.z += f.x; a0.w += f.y;
    }
    a0.x += a1.x; a0.y += a1.y; a0.z += a1.z; a0.w += a1.w;
    float id = g_invd[gwarp];
    float4 rv = *(const float4*)(R + (size_t)gwarp * F + lane * 4);
    float4 bv = *(const float4*)(bias + lane * 4);
    float4 o;
    o.x = a0.x * id + bv.x + rv.x;
    o.y = a0.y * id + bv.y + rv.y;
    o.z = a0.z * id + bv.z + rv.z;
    o.w = a0.w * id + bv.w + rv.w;
    if (doRelu) {
        o.x = fmaxf(o.x, 0.f); o.y = fmaxf(o.y, 0.f);
        o.z = fmaxf(o.z, 0.f); o.w = fmaxf(o.w, 0.f);
    }

    if (writePacked) {
        // split to bf16 hi/lo and store in the permuted packed-A layout
        float hx = __bfloat162float(__float2bfloat16(o.x));
        float hy = __bfloat162float(__float2bfloat16(o.y));
        float hz = __bfloat162float(__float2bfloat16(o.z));
        float hw = __bfloat162float(__float2bfloat16(o.w));
        size_t p0 = (size_t)gwarp * WROW + kkpos(2 * lane);
        size_t p1 = (size_t)gwarp * WROW + kkpos(2 * lane + 1);
        g_ahi[p0] = pack_bf2(o.x, o.y);
        g_ahi[p1] = pack_bf2(o.z, o.w);
        g_alo[p0] = pack_bf2(o.x - hx, o.y - hy);
        g_alo[p1] = pack_bf2(o.z - hz, o.w - hw);
        return;
    }

    *(float4*)(O + (size_t)gwarp * F + lane * 4) = o;

    if (Wl2) {
        // fused tiny GEMM: z = o @ Wl2, r2 = o @ Wr2  (full row is in this warp)
        float ov[4] = { o.x, o.y, o.z, o.w };
        float zl[4] = { 0.f, 0.f, 0.f, 0.f };
        float zr[4] = { 0.f, 0.f, 0.f, 0.f };
        #pragma unroll
        for (int c = 0; c < 4; c++) {
            int k = lane * 4 + c;
            #pragma unroll
            for (int j = 0; j < 4; j++) {
                zl[j] += ov[c] * sWl[k * CC + j];
                zr[j] += ov[c] * sWr[k * CC + j];
            }
        }
        #pragma unroll
        for (int off = 16; off > 0; off >>= 1) {
            #pragma unroll
            for (int j = 0; j < 4; j++) {
                zl[j] += __shfl_down_sync(0xFFFFFFFFu, zl[j], off);
                zr[j] += __shfl_down_sync(0xFFFFFFFFu, zr[j], off);
            }
        }
        if (lane == 0) {
            *(float4*)(g_z  + (size_t)gwarp * CC) = make_float4(zl[0], zl[1], zl[2], zl[3]);
            *(float4*)(g_r2 + (size_t)gwarp * CC) = make_float4(zr[0], zr[1], zr[2], zr[3]);
        }
    }
}

// ---------------- 4-wide aggregation + final epilogue; writes out twice ----------------
__global__ void k_agg4(const float* __restrict__ b2, float* __restrict__ out, int n) {
    int gwarp = (blockIdx.x * blockDim.x + threadIdx.x) >> 5;
    int lane = threadIdx.x & 31;
    if (gwarp >= n) return;
    int s = g_ptr[gwarp], e = g_ptr[gwarp + 1];
    float4 acc = make_float4(0.f, 0.f, 0.f, 0.f);
    for (int i = s + lane; i < e; i += 32) {
        int nb = g_idx[i];
        float4 z = *(const float4*)(g_z + (size_t)nb * CC);
        acc.x += z.x; acc.y += z.y; acc.z += z.z; acc.w += z.w;
    }
    #pragma unroll
    for (int off = 16; off > 0; off >>= 1) {
        acc.x += __shfl_xor_sync(0xFFFFFFFFu, acc.x, off);
        acc.y += __shfl_xor_sync(0xFFFFFFFFu, acc.y, off);
        acc.z += __shfl_xor_sync(0xFFFFFFFFu, acc.z, off);
        acc.w += __shfl_xor_sync(0xFFFFFFFFu, acc.w, off);
    }
    if (lane == 0) {
        float id = g_invd[gwarp];
        float4 r = *(const float4*)(g_r2 + (size_t)gwarp * CC);
        float4 b = *(const float4*)(b2);
        float4 o;
        o.x = acc.x * id + b.x + r.x;
        o.y = acc.y * id + b.y + r.y;
        o.z = acc.z * id + b.z + r.z;
        o.w = acc.w * id + b.w + r.w;
        *(float4*)(out + (size_t)gwarp * CC) = o;
        *(float4*)(out + (size_t)n * CC + (size_t)gwarp * CC) = o;
    }
}

// ---------------- launch ----------------
static cudaStream_t g_s2 = nullptr;
static cudaEvent_t g_eFork = nullptr;
static cudaEvent_t g_eW = nullptr;
static cudaEvent_t g_eJoin = nullptr;

extern "C" void kernel_launch(void* const* d_in, const int* in_sizes, int n_in,
                              void* d_out, int out_size) {
    const float* x   = (const float*)d_in[0];
    const int*   ei  = (const int*)d_in[1];
    const float* Wl0 = (const float*)d_in[2];
    const float* bl0 = (const float*)d_in[3];
    const float* Wr0 = (const float*)d_in[4];
    const float* Wl1 = (const float*)d_in[5];
    const float* bl1 = (const float*)d_in[6];
    const float* Wr1 = (const float*)d_in[7];
    const float* Wl2 = (const float*)d_in[8];
    const float* bl2 = (const float*)d_in[9];
    const float* Wr2 = (const float*)d_in[10];

    int N = in_sizes[0] / F;
    int E = in_sizes[1] / 2;
    const int* src = ei;
    const int* dst = ei + E;

    float* out = (float*)d_out;
    float* h2  = out + (size_t)2 * N * CC;   // layout: out | out | h2

    void* p;
    cudaGetSymbolAddress(&p, g_y16); uint32_t* yb16 = (uint32_t*)p;
    cudaGetSymbolAddress(&p, g_r);   float* rb = (float*)p;
    cudaGetSymbolAddress(&p, g_wp_hi); uint32_t* whi = (uint32_t*)p;
    cudaGetSymbolAddress(&p, g_wp_lo); uint32_t* wlo = (uint32_t*)p;

    if (!g_s2) {
        cudaStreamCreateWithFlags(&g_s2, cudaStreamNonBlocking);
        cudaEventCreateWithFlags(&g_eFork, cudaEventDisableTiming);
        cudaEventCreateWithFlags(&g_eW, cudaEventDisableTiming);
        cudaEventCreateWithFlags(&g_eJoin, cudaEventDisableTiming);
    }

    cudaFuncSetAttribute(k_mma64, cudaFuncAttributeMaxDynamicSharedMemorySize, SM_GEMM_TOTAL);

    int gemmBlocks = (N + 63) / 64;
    int warpBlocks = (N * 32 + 255) / 256;
    int nScanBlocks = (N + SCAN_B - 1) / SCAN_B;

    // ---- fork: weight prep + CSR build on g_s2, A prep + GEMM on main stream ----
    cudaEventRecord(g_eFork, 0);
    cudaStreamWaitEvent(g_s2, g_eFork, 0);

    // branch B (g_s2): weight prep first (needed by GEMM), then CSR chain
    k_prepW4<<<dim3(32, 4), 256, 0, g_s2>>>(Wl0, Wr0, Wl1, Wr1);
    cudaEventRecord(g_eW, g_s2);
    k_init<<<(N + 255) / 256, 256, 0, g_s2>>>(N);
    k_hist<<<(E + 255) / 256, 256, 0, g_s2>>>(dst, E);
    k_scan1<<<nScanBlocks, SCAN_B, 0, g_s2>>>(N);
    k_scan2<<<1, 256, 0, g_s2>>>(nScanBlocks);
    k_scan3<<<nScanBlocks, SCAN_B, 0, g_s2>>>(N);
    k_fill<<<(E + 255) / 256, 256, 0, g_s2>>>(src, dst, E);
    cudaEventRecord(g_eJoin, g_s2);

    // branch A (main stream): A prep, then layer-0 GEMM (waits for weights)
    k_prepA<<<(N * 32 + 255) / 256, 256>>>(x, N);
    cudaStreamWaitEvent(0, g_eW, 0);
    k_mma64<<<dim3(gemmBlocks, 4), 256, SM_GEMM_TOTAL>>>(whi, wlo, yb16, rb, N);

    // ---- join: aggregation needs both CSR (g_ptr/invd/idx) and y/r ----
    cudaStreamWaitEvent(0, g_eJoin, 0);

    // layer 0 aggregation (fp16 gather) -> packed bf16 A for layer 1
    k_agg128<<<warpBlocks, 256>>>(yb16, rb, bl0, nullptr, N, 1, 1, nullptr, nullptr);

    // layer 1: GEMM from packed A, then aggregation with fused layer-2 tiny GEMM
    k_mma64<<<dim3(gemmBlocks, 4), 256, SM_GEMM_TOTAL>>>(whi + 2 * WSZ, wlo + 2 * WSZ, yb16, rb, N);
    k_agg128<<<warpBlocks, 256>>>(yb16, rb, bl1, h2, N, 0, 0, Wl2, Wr2);

    // layer 2 aggregation: out = agg(z)*invd + bl2 + r2 (written twice)
    k_agg4<<<warpBlocks, 256>>>(bl2, out, N);
}